// round 11
// baseline (speedup 1.0000x reference)
#include <cuda_runtime.h>
#include <math.h>

// TimeLSTMHyp: B=64, S=128, H=I=512
// Strategy:
//   1) Precompute full mobius_matvec(U_g, x) for all (b,s,g): one big GEMM + scaling pass.
//   2) Host loop over 128 steps (captured into the graph):
//        gemm_step: z = [h|c] @ Wbig^T  (2048 gate cols from h, 512 W_d cols from c), split-K=2
//        elem_step: all Poincare-ball elementwise math, one block per batch row b.

#define MIN_NORM 1e-15f

// ---------------- static device scratch (no allocations allowed) ----------------
__device__ float g_mu[8192u * 2048u];   // precomputed mobius_matvec(U_g, x): [b*128+s][g*512+j]  (64 MB)
__device__ float g_wbig[2560 * 512];    // rows 0..2047: rearranged W_all (gate-major); rows 2048..2559: W_d
__device__ float g_z[2 * 64 * 2560];    // split-K partial GEMM results per step
__device__ float g_h[64 * 512];         // recurrent h state
__device__ float g_c[64 * 512];         // recurrent c state

// ---------------- helpers ----------------
__device__ __forceinline__ float artanhc(float x) {
    x = fminf(fmaxf(x, -1.0f + 1e-5f), 1.0f - 1e-5f);
    return atanhf(x);
}
__device__ __forceinline__ float clampn(float sumsq) {   // ||.|| with MIN_NORM clamp, from sum of squares
    return fmaxf(sqrtf(sumsq), MIN_NORM);
}
__device__ __forceinline__ float sigm(float x) { return 1.0f / (1.0f + expf(-x)); }

// Multi-value block-wide sum reduction (blockDim.x = 512, 16 warps), result broadcast to all threads.
template <int N>
__device__ __forceinline__ void block_reduce_sum(float* v) {
    __shared__ float sh[N][17];
    const int lane = threadIdx.x & 31;
    const int wid  = threadIdx.x >> 5;
    #pragma unroll
    for (int i = 0; i < N; i++) {
        float x = v[i];
        #pragma unroll
        for (int o = 16; o > 0; o >>= 1) x += __shfl_xor_sync(0xffffffffu, x, o);
        if (lane == 0) sh[i][wid] = x;
    }
    __syncthreads();
    if (wid == 0) {
        const int nw = blockDim.x >> 5;
        #pragma unroll
        for (int i = 0; i < N; i++) {
            float x = (lane < nw) ? sh[i][lane] : 0.0f;
            #pragma unroll
            for (int o = 8; o > 0; o >>= 1) x += __shfl_xor_sync(0xffffffffu, x, o);
            if (lane == 0) sh[i][16] = x;
        }
    }
    __syncthreads();
    #pragma unroll
    for (int i = 0; i < N; i++) v[i] = sh[i][16];
    __syncthreads();   // protect shared reuse across successive calls
}

// ---------------- weight rearrangement ----------------
// Wbig[m][k], m<2048: gate g=m/512, j=m%512 -> W_all[j, g*512+k]  (so z[b,m] = sum_k h[b,k]*W_g[j,k])
// m>=2048: W_d[m-2048][k]
__global__ void prep_w(const float* __restrict__ Wall, const float* __restrict__ Wd) {
    int idx = blockIdx.x * blockDim.x + threadIdx.x;
    if (idx >= 2560 * 512) return;
    int m = idx >> 9, k = idx & 511;
    float v;
    if (m < 2048) {
        int g = m >> 9, jj = m & 511;
        v = Wall[jj * 2048 + (g << 9) + k];
    } else {
        v = Wd[(m - 2048) * 512 + k];
    }
    g_wbig[idx] = v;
}

// ---------------- precompute GEMM: g_mu[r][m] = sum_k X[r,k]*U_all[m,k] ----------------
// M=8192, N=2048, K=512.  BM=BN=64, BK=16, 256 threads, 4x4 micro-tile.
__global__ void __launch_bounds__(256) gemm_pre(const float* __restrict__ A, const float* __restrict__ U) {
    __shared__ float As[16][68];
    __shared__ float Bs[16][68];
    const int bx = blockIdx.x;   // N tile (32)
    const int by = blockIdx.y;   // M tile (128)
    const int tid = threadIdx.x;
    const int lr  = tid >> 2;          // 0..63
    const int lc4 = (tid & 3) << 2;    // 0,4,8,12
    const float* Ar = A + ((size_t)(by * 64 + lr)) * 512;
    const float* Ur = U + ((size_t)(bx * 64 + lr)) * 512;
    const int trow = (tid >> 4) << 2;
    const int tcol = (tid & 15) << 2;
    float acc[4][4] = {};
    for (int k0 = 0; k0 < 512; k0 += 16) {
        float4 av = *(const float4*)(Ar + k0 + lc4);
        float4 bv = *(const float4*)(Ur + k0 + lc4);
        __syncthreads();
        As[lc4 + 0][lr] = av.x; As[lc4 + 1][lr] = av.y; As[lc4 + 2][lr] = av.z; As[lc4 + 3][lr] = av.w;
        Bs[lc4 + 0][lr] = bv.x; Bs[lc4 + 1][lr] = bv.y; Bs[lc4 + 2][lr] = bv.z; Bs[lc4 + 3][lr] = bv.w;
        __syncthreads();
        #pragma unroll
        for (int kk = 0; kk < 16; kk++) {
            float4 a = *(const float4*)&As[kk][trow];
            float4 b = *(const float4*)&Bs[kk][tcol];
            acc[0][0] += a.x * b.x; acc[0][1] += a.x * b.y; acc[0][2] += a.x * b.z; acc[0][3] += a.x * b.w;
            acc[1][0] += a.y * b.x; acc[1][1] += a.y * b.y; acc[1][2] += a.y * b.z; acc[1][3] += a.y * b.w;
            acc[2][0] += a.z * b.x; acc[2][1] += a.z * b.y; acc[2][2] += a.z * b.z; acc[2][3] += a.z * b.w;
            acc[3][0] += a.w * b.x; acc[3][1] += a.w * b.y; acc[3][2] += a.w * b.z; acc[3][3] += a.w * b.w;
        }
    }
    #pragma unroll
    for (int i = 0; i < 4; i++) {
        float* C = g_mu + ((size_t)(by * 64 + trow + i)) * 2048 + bx * 64 + tcol;
        *(float4*)C = make_float4(acc[i][0], acc[i][1], acc[i][2], acc[i][3]);
    }
}

// ---------------- scale precomputed mu: full mobius_matvec nonlinearity ----------------
__global__ void scale_mu(const float* __restrict__ X) {
    const int r = blockIdx.x;       // 0..8191
    const int j = threadIdx.x;      // 0..511
    float xj = X[(size_t)r * 512 + j];
    float* mrow = g_mu + (size_t)r * 2048;
    float m0 = mrow[j], m1 = mrow[512 + j], m2 = mrow[1024 + j], m3 = mrow[1536 + j];
    float v[5] = {xj * xj, m0 * m0, m1 * m1, m2 * m2, m3 * m3};
    block_reduce_sum<5>(v);
    float xn = clampn(v[0]);
    float at = artanhc(xn);
    float n0 = clampn(v[1]); mrow[j]        = tanhf(n0 / xn * at) / n0 * m0;
    float n1 = clampn(v[2]); mrow[512 + j]  = tanhf(n1 / xn * at) / n1 * m1;
    float n2 = clampn(v[3]); mrow[1024 + j] = tanhf(n2 / xn * at) / n2 * m2;
    float n3 = clampn(v[4]); mrow[1536 + j] = tanhf(n3 / xn * at) / n3 * m3;
}

// ---------------- per-step GEMM: z[64][2560] = [h|c] @ Wbig^T, split-K=2 ----------------
// BM=64 (all rows), BN=16, BK=16, 128 threads, 2x4 micro. grid (160, 2).
__global__ void __launch_bounds__(128) gemm_step() {
    __shared__ float As[16][68];
    __shared__ float Bs[16][16];
    const int bx  = blockIdx.x;      // col tile 0..159
    const int kh  = blockIdx.y;      // K half 0..1
    const int tid = threadIdx.x;
    const int col0 = bx * 16;
    const float* A  = (col0 < 2048) ? g_h : g_c;
    const float* Bw = g_wbig + (size_t)col0 * 512;
    const int lr  = tid >> 2;          // 0..31
    const int lc4 = (tid & 3) << 2;
    const int rg  = tid & 31;          // row group (rows 2rg, 2rg+1)
    const int cg  = tid >> 5;          // col group (cols 4cg..4cg+3)
    float acc[2][4] = {};
    const int kend = kh * 256 + 256;
    for (int k0 = kh * 256; k0 < kend; k0 += 16) {
        float4 a0 = *(const float4*)(A + (size_t)lr * 512 + k0 + lc4);
        float4 a1 = *(const float4*)(A + (size_t)(lr + 32) * 512 + k0 + lc4);
        float4 bv = make_float4(0.f, 0.f, 0.f, 0.f);
        if (tid < 64) bv = *(const float4*)(Bw + (size_t)(tid >> 2) * 512 + k0 + ((tid & 3) << 2));
        __syncthreads();
        As[lc4 + 0][lr] = a0.x; As[lc4 + 1][lr] = a0.y; As[lc4 + 2][lr] = a0.z; As[lc4 + 3][lr] = a0.w;
        As[lc4 + 0][lr + 32] = a1.x; As[lc4 + 1][lr + 32] = a1.y; As[lc4 + 2][lr + 32] = a1.z; As[lc4 + 3][lr + 32] = a1.w;
        if (tid < 64) {
            int br = tid >> 2, bc4 = (tid & 3) << 2;
            Bs[bc4 + 0][br] = bv.x; Bs[bc4 + 1][br] = bv.y; Bs[bc4 + 2][br] = bv.z; Bs[bc4 + 3][br] = bv.w;
        }
        __syncthreads();
        #pragma unroll
        for (int kk = 0; kk < 16; kk++) {
            float2 a  = *(const float2*)&As[kk][rg * 2];
            float4 bq = *(const float4*)&Bs[kk][cg * 4];
            acc[0][0] += a.x * bq.x; acc[0][1] += a.x * bq.y; acc[0][2] += a.x * bq.z; acc[0][3] += a.x * bq.w;
            acc[1][0] += a.y * bq.x; acc[1][1] += a.y * bq.y; acc[1][2] += a.y * bq.z; acc[1][3] += a.y * bq.w;
        }
    }
    const int row0 = rg * 2;
    float* Z = g_z + (size_t)kh * 64 * 2560;
    *(float4*)&Z[(size_t)(row0 + 0) * 2560 + col0 + cg * 4] = make_float4(acc[0][0], acc[0][1], acc[0][2], acc[0][3]);
    *(float4*)&Z[(size_t)(row0 + 1) * 2560 + col0 + cg * 4] = make_float4(acc[1][0], acc[1][1], acc[1][2], acc[1][3]);
}

// ---------------- per-step elementwise (one block per b, 512 threads = H) ----------------
__global__ void __launch_bounds__(512) elem_step(int step, const float* __restrict__ ts, float* __restrict__ out) {
    const int b = blockIdx.x;
    const int j = threadIdx.x;
    const float t = ts[b * 128 + step];
    float cj = g_c[b * 512 + j];
    float hj = g_h[b * 512 + j];
    const float* z0 = g_z + (size_t)b * 2560;
    const float* z1 = g_z + (size_t)(64 + b) * 2560;
    float zg[4], mug[4];
    #pragma unroll
    for (int g = 0; g < 4; g++) zg[g] = z0[g * 512 + j] + z1[g * 512 + j];
    float mcd = z0[2048 + j] + z1[2048 + j];
    const float* mup = g_mu + ((size_t)(b * 128 + step)) * 2048;
    #pragma unroll
    for (int g = 0; g < 4; g++) mug[g] = mup[g * 512 + j];

    // P1: ||c||^2, ||h||^2, ||mcd||^2, ||z_g||^2 x4
    float r1[7] = {cj * cj, hj * hj, mcd * mcd, zg[0] * zg[0], zg[1] * zg[1], zg[2] * zg[2], zg[3] * zg[3]};
    block_reduce_sum<7>(r1);
    const float c2 = r1[0];
    const float cn = clampn(c2), hn = clampn(r1[1]), mcdn = clampn(r1[2]);
    const float athn = artanhc(hn);
    // M1 = mobius_matvec(W_d, c)
    const float M1 = tanhf(mcdn / cn * artanhc(cn)) / mcdn * mcd;
    // Wp_g = mobius_matvec(W_g, h)
    float tgh[4], Wp[4];
    #pragma unroll
    for (int g = 0; g < 4; g++) {
        float zn = clampn(r1[3 + g]);
        tgh[g] = tanhf(zn / hn * athn);
        Wp[g]  = tgh[g] / zn * zg[g];
    }

    // P2: ||M1||^2, ||mu_g||^2 x4, <Wp_g, mu_g> x4
    float r2[9] = {M1 * M1, mug[0] * mug[0], mug[1] * mug[1], mug[2] * mug[2], mug[3] * mug[3],
                   Wp[0] * mug[0], Wp[1] * mug[1], Wp[2] * mug[2], Wp[3] * mug[3]};
    block_reduce_sum<9>(r2);
    const float M1n = clampn(r2[0]);
    const float T = tanhf(artanhc(M1n) / M1n * M1);   // tanh(logmap0(M1))
    float sg[4];
    #pragma unroll
    for (int g = 0; g < 4; g++) {       // s_g = mobius_add(Wp_g, mu_g)
        float x2 = tgh[g] * tgh[g], y2 = r2[1 + g], xy = r2[5 + g];
        float den = fmaxf(1.f + 2.f * xy + x2 * y2, MIN_NORM);
        sg[g] = ((1.f + 2.f * xy + y2) * Wp[g] + (1.f - x2) * mug[g]) / den;
    }

    // P3: ||T||^2, ||s_g||^2 x4
    float r3[5] = {T * T, sg[0] * sg[0], sg[1] * sg[1], sg[2] * sg[2], sg[3] * sg[3]};
    block_reduce_sum<5>(r3);
    const float Tn = clampn(r3[0]);
    const float cs1 = tanhf(Tn) / Tn * T;             // c_s1 = expmap0(T)
    float gate[4];
    #pragma unroll
    for (int g = 0; g < 4; g++) {                     // sigmoid(logmap0(s_g))
        float sn = clampn(r3[1 + g]);
        gate[g] = sigm(artanhc(sn) / sn * sg[g]);
    }
    const float gf = gate[0], gi = gate[1], go = gate[2], ct = gate[3];
    out[((size_t)(b * 128 + step)) * 512 + j] = go;   // outputs = o gate

    // P4: ||c_s1||^2, <-c_s1, c>, ||c_tmp||^2, ||i*c_tmp||^2
    const float ict = gi * ct;
    float r4[4] = {cs1 * cs1, -cs1 * cj, ct * ct, ict * ict};
    block_reduce_sum<4>(r4);
    const float cs1_2 = r4[0], xy1 = r4[1];
    // c_s2 = mobius_pw_mul(c_s1, t_vec)
    const float ta = fabsf(t);
    const float xn_t  = fmaxf(ta * sqrtf(512.0f), MIN_NORM);
    const float wxn_t = fmaxf(ta * sqrtf(cs1_2), MIN_NORM);
    const float cs2 = tanhf(wxn_t / xn_t * artanhc(xn_t)) / wxn_t * (t * cs1);
    // c_l = mobius_add(-c_s1, c)
    const float denl = fmaxf(1.f + 2.f * xy1 + cs1_2 * c2, MIN_NORM);
    const float cl = ((1.f + 2.f * xy1 + c2) * (-cs1) + (1.f - cs1_2) * cj) / denl;
    // P = mobius_pw_mul(i, c_tmp)
    const float ctn = clampn(r4[2]), ictn = clampn(r4[3]);
    const float P = tanhf(ictn / ctn * artanhc(ctn)) / ictn * ict;

    // P5: c_adj = mobius_add(c_l, c_s2)
    float r5[3] = {cl * cl, cs2 * cs2, cl * cs2};
    block_reduce_sum<3>(r5);
    const float den5 = fmaxf(1.f + 2.f * r5[2] + r5[0] * r5[1], MIN_NORM);
    const float cadj = ((1.f + 2.f * r5[2] + r5[1]) * cl + (1.f - r5[0]) * cs2) / den5;

    // P6: ||c_adj||^2, ||f*c_adj||^2, ||P||^2
    const float fca = gf * cadj;
    float r6[3] = {cadj * cadj, fca * fca, P * P};
    block_reduce_sum<3>(r6);
    const float cadjn = clampn(r6[0]), fcan = clampn(r6[1]);
    const float Q = tanhf(fcan / cadjn * artanhc(cadjn)) / fcan * fca;   // pw_mul(f, c_adj)
    const float P2s = r6[2];

    // P7: c_new = mobius_add(P, Q)
    float r7[2] = {Q * Q, P * Q};
    block_reduce_sum<2>(r7);
    const float den7 = fmaxf(1.f + 2.f * r7[1] + P2s * r7[0], MIN_NORM);
    const float cnew = ((1.f + 2.f * r7[1] + r7[0]) * P + (1.f - P2s) * Q) / den7;

    // P8: e = expmap0(tanh(c_new))
    const float u = tanhf(cnew);
    float r8[1] = {u * u};
    block_reduce_sum<1>(r8);
    const float un = clampn(r8[0]);
    const float e = tanhf(un) / un * u;

    // P9: h_new = pw_mul(o, e)
    const float oe = go * e;
    float r9[2] = {e * e, oe * oe};
    block_reduce_sum<2>(r9);
    const float en = clampn(r9[0]), oen = clampn(r9[1]);
    const float hnew = tanhf(oen / en * artanhc(en)) / oen * oe;

    g_h[b * 512 + j] = hnew;
    g_c[b * 512 + j] = cnew;
    if (step == 127) {
        out[(size_t)64 * 128 * 512 + (size_t)b * 512 + j] = hnew;
        out[(size_t)64 * 128 * 512 + (size_t)64 * 512 + (size_t)b * 512 + j] = cnew;
    }
}

// ---------------- launch ----------------
extern "C" void kernel_launch(void* const* d_in, const int* in_sizes, int n_in,
                              void* d_out, int out_size) {
    const float* inputs = (const float*)d_in[0];   // [64,128,512]
    const float* ts     = (const float*)d_in[1];   // [64,128]
    const float* h0     = (const float*)d_in[2];   // [64,512]
    const float* c0     = (const float*)d_in[3];   // [64,512]
    const float* Wall   = (const float*)d_in[4];   // [512,2048]
    const float* Uall   = (const float*)d_in[5];   // [2048,512]
    const float* Wd     = (const float*)d_in[6];   // [512,512]
    float* out = (float*)d_out;

    cudaMemcpyToSymbolAsync(g_h, h0, 64 * 512 * sizeof(float), 0, cudaMemcpyDeviceToDevice, 0);
    cudaMemcpyToSymbolAsync(g_c, c0, 64 * 512 * sizeof(float), 0, cudaMemcpyDeviceToDevice, 0);

    prep_w<<<(2560 * 512 + 255) / 256, 256>>>(Wall, Wd);
    gemm_pre<<<dim3(32, 128), 256>>>(inputs, Uall);
    scale_mu<<<8192, 512>>>(inputs);

    for (int t = 0; t < 128; t++) {
        gemm_step<<<dim3(160, 2), 128>>>();
        elem_step<<<64, 512>>>(t, ts, out);
    }
}

// round 12
// speedup vs baseline: 1.2901x; 1.2901x over previous
#include <cuda_runtime.h>
#include <math.h>

// TimeLSTMHyp: B=64, S=128, H=I=512
//  1) Precompute mobius_matvec(U_g, x) for all (b,s,g): one big GEMM (FFMA2 / f32x2 packed) + scaling pass.
//  2) 128 captured steps: gemm_step (split-K=16, 640 blocks, crossbar-balanced 4x4 micro)
//     + elem_step (all Poincare-ball elementwise math, sums the 16 split-K partials).

#define MIN_NORM 1e-15f
#define KSLICES 16

// ---------------- static device scratch (no allocations allowed) ----------------
__device__ float g_mu[8192u * 2048u];        // precomputed mobius_matvec(U_g, x): [b*128+s][g*512+j] (64 MB)
__device__ float g_wbig[2560 * 512];         // rows 0..2047: gate-major W_all; rows 2048..2559: W_d
__device__ float g_z[KSLICES * 64 * 2560];   // split-K partial GEMM results per step (10.5 MB)
__device__ float g_h[64 * 512];              // recurrent h state
__device__ float g_c[64 * 512];              // recurrent c state

// ---------------- helpers ----------------
__device__ __forceinline__ float artanhc(float x) {
    x = fminf(fmaxf(x, -1.0f + 1e-5f), 1.0f - 1e-5f);
    return atanhf(x);
}
__device__ __forceinline__ float clampn(float sumsq) {
    return fmaxf(sqrtf(sumsq), MIN_NORM);
}
__device__ __forceinline__ float sigm(float x) { return 1.0f / (1.0f + expf(-x)); }

// packed f32x2 (FFMA2) helpers — sm_100+ PTX
__device__ __forceinline__ unsigned long long dup_f32(float x) {
    unsigned long long r;
    asm("mov.b64 %0, {%1, %1};" : "=l"(r) : "f"(x));
    return r;
}
__device__ __forceinline__ void fma_x2(unsigned long long& d, unsigned long long a, unsigned long long b) {
    asm("fma.rn.f32x2 %0, %1, %2, %0;" : "+l"(d) : "l"(a), "l"(b));
}
__device__ __forceinline__ float2 unpack_x2(unsigned long long v) {
    float2 r;
    asm("mov.b64 {%0, %1}, %2;" : "=f"(r.x), "=f"(r.y) : "l"(v));
    return r;
}

// Multi-value block-wide sum reduction (blockDim.x = 512), result broadcast to all threads.
template <int N>
__device__ __forceinline__ void block_reduce_sum(float* v) {
    __shared__ float sh[N][17];
    const int lane = threadIdx.x & 31;
    const int wid  = threadIdx.x >> 5;
    #pragma unroll
    for (int i = 0; i < N; i++) {
        float x = v[i];
        #pragma unroll
        for (int o = 16; o > 0; o >>= 1) x += __shfl_xor_sync(0xffffffffu, x, o);
        if (lane == 0) sh[i][wid] = x;
    }
    __syncthreads();
    if (wid == 0) {
        const int nw = blockDim.x >> 5;
        #pragma unroll
        for (int i = 0; i < N; i++) {
            float x = (lane < nw) ? sh[i][lane] : 0.0f;
            #pragma unroll
            for (int o = 8; o > 0; o >>= 1) x += __shfl_xor_sync(0xffffffffu, x, o);
            if (lane == 0) sh[i][16] = x;
        }
    }
    __syncthreads();
    #pragma unroll
    for (int i = 0; i < N; i++) v[i] = sh[i][16];
    __syncthreads();
}

// ---------------- weight rearrangement ----------------
__global__ void prep_w(const float* __restrict__ Wall, const float* __restrict__ Wd) {
    int idx = blockIdx.x * blockDim.x + threadIdx.x;
    if (idx >= 2560 * 512) return;
    int m = idx >> 9, k = idx & 511;
    float v;
    if (m < 2048) {
        int g = m >> 9, jj = m & 511;
        v = Wall[jj * 2048 + (g << 9) + k];
    } else {
        v = Wd[(m - 2048) * 512 + k];
    }
    g_wbig[idx] = v;
}

// ---------------- precompute GEMM: g_mu[r][m] = sum_k X[r,k]*U_all[m,k] ----------------
// M=8192, N=2048, K=512. BM=BN=128, BK=16, 256 threads, 8x8 micro via packed f32x2.
__global__ void __launch_bounds__(256) gemm_pre(const float* __restrict__ A, const float* __restrict__ U) {
    __shared__ float As[16][132];
    __shared__ float Bs[16][132];
    const int bx = blockIdx.x;   // N tile (16)
    const int by = blockIdx.y;   // M tile (64)
    const int tid = threadIdx.x;
    const int lr  = tid >> 1;          // 0..127
    const int lc8 = (tid & 1) << 3;    // 0 or 8
    const float* Ar = A + (size_t)(by * 128 + lr) * 512 + lc8;
    const float* Ur = U + (size_t)(bx * 128 + lr) * 512 + lc8;
    const int ty = tid >> 4, tx = tid & 15;

    unsigned long long acc[4][8];   // 4 row-pairs (8 rows) x 8 cols
    #pragma unroll
    for (int i = 0; i < 4; i++)
        #pragma unroll
        for (int j = 0; j < 8; j++) acc[i][j] = 0ull;

    for (int k0 = 0; k0 < 512; k0 += 16) {
        float4 a0 = *(const float4*)(Ar + k0);
        float4 a1 = *(const float4*)(Ar + k0 + 4);
        float4 b0 = *(const float4*)(Ur + k0);
        float4 b1 = *(const float4*)(Ur + k0 + 4);
        __syncthreads();
        As[lc8 + 0][lr] = a0.x; As[lc8 + 1][lr] = a0.y; As[lc8 + 2][lr] = a0.z; As[lc8 + 3][lr] = a0.w;
        As[lc8 + 4][lr] = a1.x; As[lc8 + 5][lr] = a1.y; As[lc8 + 6][lr] = a1.z; As[lc8 + 7][lr] = a1.w;
        Bs[lc8 + 0][lr] = b0.x; Bs[lc8 + 1][lr] = b0.y; Bs[lc8 + 2][lr] = b0.z; Bs[lc8 + 3][lr] = b0.w;
        Bs[lc8 + 4][lr] = b1.x; Bs[lc8 + 5][lr] = b1.y; Bs[lc8 + 6][lr] = b1.z; Bs[lc8 + 7][lr] = b1.w;
        __syncthreads();
        #pragma unroll
        for (int kk = 0; kk < 16; kk++) {
            // a: rows 8ty..8ty+7 as 4 natural f32x2 pairs (16B-aligned: row stride 132*4=528B)
            ulonglong2 apA = *(const ulonglong2*)&As[kk][ty * 8];
            ulonglong2 apB = *(const ulonglong2*)&As[kk][ty * 8 + 4];
            #pragma unroll
            for (int j = 0; j < 8; j++) {
                unsigned long long bd = dup_f32(Bs[kk][tx + 16 * j]);  // strided cols: conflict-free LDS.32
                fma_x2(acc[0][j], apA.x, bd);
                fma_x2(acc[1][j], apA.y, bd);
                fma_x2(acc[2][j], apB.x, bd);
                fma_x2(acc[3][j], apB.y, bd);
            }
        }
    }
    // epilogue: row r = by*128 + ty*8 + 2*ip + half; col = bx*128 + 16*j + tx (coalesced across tx)
    float* C = g_mu + (size_t)(by * 128 + ty * 8) * 2048 + bx * 128 + tx;
    #pragma unroll
    for (int ip = 0; ip < 4; ip++) {
        #pragma unroll
        for (int j = 0; j < 8; j++) {
            float2 v = unpack_x2(acc[ip][j]);
            C[(size_t)(2 * ip + 0) * 2048 + j * 16] = v.x;
            C[(size_t)(2 * ip + 1) * 2048 + j * 16] = v.y;
        }
    }
}

// ---------------- scale precomputed mu: full mobius_matvec nonlinearity ----------------
__global__ void scale_mu(const float* __restrict__ X) {
    const int r = blockIdx.x;       // 0..8191
    const int j = threadIdx.x;      // 0..511
    float xj = X[(size_t)r * 512 + j];
    float* mrow = g_mu + (size_t)r * 2048;
    float m0 = mrow[j], m1 = mrow[512 + j], m2 = mrow[1024 + j], m3 = mrow[1536 + j];
    float v[5] = {xj * xj, m0 * m0, m1 * m1, m2 * m2, m3 * m3};
    block_reduce_sum<5>(v);
    float xn = clampn(v[0]);
    float at = artanhc(xn);
    float n0 = clampn(v[1]); mrow[j]        = tanhf(n0 / xn * at) / n0 * m0;
    float n1 = clampn(v[2]); mrow[512 + j]  = tanhf(n1 / xn * at) / n1 * m1;
    float n2 = clampn(v[3]); mrow[1024 + j] = tanhf(n2 / xn * at) / n2 * m2;
    float n3 = clampn(v[4]); mrow[1536 + j] = tanhf(n3 / xn * at) / n3 * m3;
}

// ---------------- per-step GEMM: z = [h|c] @ Wbig^T, split-K=16 ----------------
// grid (40, 16): col-tile (BN=64) x K-chunk (32). 256 threads, BM=64, BK=16, 4x4 micro.
// This shape is smem-crossbar-balanced: 2 LDS.128 per 16 FFMA saturates at FFMA peak.
__global__ void __launch_bounds__(256) gemm_step() {
    __shared__ float As[16][68];
    __shared__ float Bs[16][68];
    const int ct  = blockIdx.x;      // 0..39
    const int kc  = blockIdx.y;      // 0..15
    const int tid = threadIdx.x;
    const int col0 = ct * 64;
    const float* Ab = (ct < 32) ? g_h : g_c;
    const float* Bb = g_wbig + (size_t)col0 * 512;
    const int lr  = tid >> 2;          // 0..63
    const int lc4 = (tid & 3) << 2;
    const int ty = tid >> 4, tx = tid & 15;
    const int kb = kc * 32;
    float acc[4][4] = {};
    #pragma unroll
    for (int it = 0; it < 2; it++) {
        const int k0 = kb + it * 16;
        float4 av = *(const float4*)(Ab + (size_t)lr * 512 + k0 + lc4);
        float4 bv = *(const float4*)(Bb + (size_t)lr * 512 + k0 + lc4);
        __syncthreads();
        As[lc4 + 0][lr] = av.x; As[lc4 + 1][lr] = av.y; As[lc4 + 2][lr] = av.z; As[lc4 + 3][lr] = av.w;
        Bs[lc4 + 0][lr] = bv.x; Bs[lc4 + 1][lr] = bv.y; Bs[lc4 + 2][lr] = bv.z; Bs[lc4 + 3][lr] = bv.w;
        __syncthreads();
        #pragma unroll
        for (int kk = 0; kk < 16; kk++) {
            float4 a = *(const float4*)&As[kk][ty * 4];
            float4 b = *(const float4*)&Bs[kk][tx * 4];
            acc[0][0] += a.x * b.x; acc[0][1] += a.x * b.y; acc[0][2] += a.x * b.z; acc[0][3] += a.x * b.w;
            acc[1][0] += a.y * b.x; acc[1][1] += a.y * b.y; acc[1][2] += a.y * b.z; acc[1][3] += a.y * b.w;
            acc[2][0] += a.z * b.x; acc[2][1] += a.z * b.y; acc[2][2] += a.z * b.z; acc[2][3] += a.z * b.w;
            acc[3][0] += a.w * b.x; acc[3][1] += a.w * b.y; acc[3][2] += a.w * b.z; acc[3][3] += a.w * b.w;
        }
    }
    float* Z = g_z + (size_t)kc * 64 * 2560;
    #pragma unroll
    for (int i = 0; i < 4; i++) {
        *(float4*)&Z[(size_t)(ty * 4 + i) * 2560 + col0 + tx * 4] =
            make_float4(acc[i][0], acc[i][1], acc[i][2], acc[i][3]);
    }
}

// ---------------- per-step elementwise (one block per b, 512 threads = H) ----------------
__global__ void __launch_bounds__(512) elem_step(int step, const float* __restrict__ ts, float* __restrict__ out) {
    const int b = blockIdx.x;
    const int j = threadIdx.x;
    const float t = ts[b * 128 + step];
    float cj = g_c[b * 512 + j];
    float hj = g_h[b * 512 + j];

    float zg[4] = {0.f, 0.f, 0.f, 0.f};
    float mcd = 0.f;
    #pragma unroll
    for (int s = 0; s < KSLICES; s++) {
        const float* zp = g_z + (size_t)s * 64 * 2560 + (size_t)b * 2560;
        #pragma unroll
        for (int g = 0; g < 4; g++) zg[g] += zp[g * 512 + j];
        mcd += zp[2048 + j];
    }
    float mug[4];
    const float* mup = g_mu + ((size_t)(b * 128 + step)) * 2048;
    #pragma unroll
    for (int g = 0; g < 4; g++) mug[g] = mup[g * 512 + j];

    // P1: ||c||^2, ||h||^2, ||mcd||^2, ||z_g||^2 x4
    float r1[7] = {cj * cj, hj * hj, mcd * mcd, zg[0] * zg[0], zg[1] * zg[1], zg[2] * zg[2], zg[3] * zg[3]};
    block_reduce_sum<7>(r1);
    const float c2 = r1[0];
    const float cn = clampn(c2), hn = clampn(r1[1]), mcdn = clampn(r1[2]);
    const float athn = artanhc(hn);
    const float M1 = tanhf(mcdn / cn * artanhc(cn)) / mcdn * mcd;   // mobius_matvec(W_d, c)
    float tgh[4], Wp[4];
    #pragma unroll
    for (int g = 0; g < 4; g++) {                                   // mobius_matvec(W_g, h)
        float zn = clampn(r1[3 + g]);
        tgh[g] = tanhf(zn / hn * athn);
        Wp[g]  = tgh[g] / zn * zg[g];
    }

    // P2: ||M1||^2, ||mu_g||^2 x4, <Wp_g, mu_g> x4
    float r2[9] = {M1 * M1, mug[0] * mug[0], mug[1] * mug[1], mug[2] * mug[2], mug[3] * mug[3],
                   Wp[0] * mug[0], Wp[1] * mug[1], Wp[2] * mug[2], Wp[3] * mug[3]};
    block_reduce_sum<9>(r2);
    const float M1n = clampn(r2[0]);
    const float T = tanhf(artanhc(M1n) / M1n * M1);                 // tanh(logmap0(M1))
    float sg[4];
    #pragma unroll
    for (int g = 0; g < 4; g++) {                                   // mobius_add(Wp_g, mu_g)
        float x2 = tgh[g] * tgh[g], y2 = r2[1 + g], xy = r2[5 + g];
        float den = fmaxf(1.f + 2.f * xy + x2 * y2, MIN_NORM);
        sg[g] = ((1.f + 2.f * xy + y2) * Wp[g] + (1.f - x2) * mug[g]) / den;
    }

    // P3: ||T||^2, ||s_g||^2 x4
    float r3[5] = {T * T, sg[0] * sg[0], sg[1] * sg[1], sg[2] * sg[2], sg[3] * sg[3]};
    block_reduce_sum<5>(r3);
    const float Tn = clampn(r3[0]);
    const float cs1 = tanhf(Tn) / Tn * T;                           // expmap0(T)
    float gate[4];
    #pragma unroll
    for (int g = 0; g < 4; g++) {                                   // sigmoid(logmap0(s_g))
        float sn = clampn(r3[1 + g]);
        gate[g] = sigm(artanhc(sn) / sn * sg[g]);
    }
    const float gf = gate[0], gi = gate[1], go = gate[2], ct = gate[3];
    out[((size_t)(b * 128 + step)) * 512 + j] = go;

    // P4: ||c_s1||^2, <-c_s1, c>, ||c_tmp||^2, ||i*c_tmp||^2
    const float ict = gi * ct;
    float r4[4] = {cs1 * cs1, -cs1 * cj, ct * ct, ict * ict};
    block_reduce_sum<4>(r4);
    const float cs1_2 = r4[0], xy1 = r4[1];
    const float ta = fabsf(t);
    const float xn_t  = fmaxf(ta * sqrtf(512.0f), MIN_NORM);
    const float wxn_t = fmaxf(ta * sqrtf(cs1_2), MIN_NORM);
    const float cs2 = tanhf(wxn_t / xn_t * artanhc(xn_t)) / wxn_t * (t * cs1);  // pw_mul(c_s1, t)
    const float denl = fmaxf(1.f + 2.f * xy1 + cs1_2 * c2, MIN_NORM);
    const float cl = ((1.f + 2.f * xy1 + c2) * (-cs1) + (1.f - cs1_2) * cj) / denl;  // mobius_add(-c_s1, c)
    const float ctn = clampn(r4[2]), ictn = clampn(r4[3]);
    const float P = tanhf(ictn / ctn * artanhc(ctn)) / ictn * ict;  // pw_mul(i, c_tmp)

    // P5: c_adj = mobius_add(c_l, c_s2)
    float r5[3] = {cl * cl, cs2 * cs2, cl * cs2};
    block_reduce_sum<3>(r5);
    const float den5 = fmaxf(1.f + 2.f * r5[2] + r5[0] * r5[1], MIN_NORM);
    const float cadj = ((1.f + 2.f * r5[2] + r5[1]) * cl + (1.f - r5[0]) * cs2) / den5;

    // P6: ||c_adj||^2, ||f*c_adj||^2, ||P||^2
    const float fca = gf * cadj;
    float r6[3] = {cadj * cadj, fca * fca, P * P};
    block_reduce_sum<3>(r6);
    const float cadjn = clampn(r6[0]), fcan = clampn(r6[1]);
    const float Q = tanhf(fcan / cadjn * artanhc(cadjn)) / fcan * fca;   // pw_mul(f, c_adj)
    const float P2s = r6[2];

    // P7: c_new = mobius_add(P, Q)
    float r7[2] = {Q * Q, P * Q};
    block_reduce_sum<2>(r7);
    const float den7 = fmaxf(1.f + 2.f * r7[1] + P2s * r7[0], MIN_NORM);
    const float cnew = ((1.f + 2.f * r7[1] + r7[0]) * P + (1.f - P2s) * Q) / den7;

    // P8: e = expmap0(tanh(c_new))
    const float u = tanhf(cnew);
    float r8[1] = {u * u};
    block_reduce_sum<1>(r8);
    const float un = clampn(r8[0]);
    const float e = tanhf(un) / un * u;

    // P9: h_new = pw_mul(o, e)
    const float oe = go * e;
    float r9[2] = {e * e, oe * oe};
    block_reduce_sum<2>(r9);
    const float en = clampn(r9[0]), oen = clampn(r9[1]);
    const float hnew = tanhf(oen / en * artanhc(en)) / oen * oe;

    g_h[b * 512 + j] = hnew;
    g_c[b * 512 + j] = cnew;
    if (step == 127) {
        out[(size_t)64 * 128 * 512 + (size_t)b * 512 + j] = hnew;
        out[(size_t)64 * 128 * 512 + (size_t)64 * 512 + (size_t)b * 512 + j] = cnew;
    }
}

// ---------------- launch ----------------
extern "C" void kernel_launch(void* const* d_in, const int* in_sizes, int n_in,
                              void* d_out, int out_size) {
    const float* inputs = (const float*)d_in[0];   // [64,128,512]
    const float* ts     = (const float*)d_in[1];   // [64,128]
    const float* h0     = (const float*)d_in[2];   // [64,512]
    const float* c0     = (const float*)d_in[3];   // [64,512]
    const float* Wall   = (const float*)d_in[4];   // [512,2048]
    const float* Uall   = (const float*)d_in[5];   // [2048,512]
    const float* Wd     = (const float*)d_in[6];   // [512,512]
    float* out = (float*)d_out;

    cudaMemcpyToSymbolAsync(g_h, h0, 64 * 512 * sizeof(float), 0, cudaMemcpyDeviceToDevice, 0);
    cudaMemcpyToSymbolAsync(g_c, c0, 64 * 512 * sizeof(float), 0, cudaMemcpyDeviceToDevice, 0);

    prep_w<<<(2560 * 512 + 255) / 256, 256>>>(Wall, Wd);
    gemm_pre<<<dim3(16, 64), 256>>>(inputs, Uall);
    scale_mu<<<8192, 512>>>(inputs);

    for (int t = 0; t < 128; t++) {
        gemm_step<<<dim3(40, 16), 256>>>();
        elem_step<<<64, 512>>>(t, ts, out);
    }
}